// round 8
// baseline (speedup 1.0000x reference)
#include <cuda_runtime.h>

// Problem constants
#define BATCH 8
#define NCLS 19
#define HH 768
#define WW 768
#define HWP (HH * WW)                 // 589824
#define HWP2 (HWP / 2)                // 294912
#define N_PIX (BATCH * HWP)           // 4718592
#define N_PAIR (N_PIX / 2)            // 2359296
#define N4 (N_PIX / 4)                // 1179648
#define IGNORE_LBL 255
#define MIN_KEPT_K 262144u
#define THRESH_F 0.7f
#define ONE_BITS 0x3F800000u
#define ALMOST_ONE_BITS 0x3F7FFFFFu
#define MAIN_BLOCKS 1152              // 1152*256 == HWP/2: stride == one batch image
#define RF_BLOCKS 148                 // one block per SM: co-residency guaranteed

// Scratch (no cudaMalloc allowed). Globals are zero at module load; every
// launch self-restores the state it consumes.
__device__ float g_prob[N_PIX];                // rare path only
__device__ unsigned int g_h256[256];           // rare path: rounds 1 & 3
__device__ unsigned int g_h16[65536];          // rare path: round 2
__device__ unsigned int g_prefix;
__device__ unsigned int g_kth_bits;
__device__ unsigned int g_k;
__device__ unsigned int g_skip;                // 1 => out written by main; 2 => refine
__device__ unsigned int g_num_valid;
__device__ unsigned int g_c07;
__device__ double g_sum07;
__device__ double g_sumall;
__device__ unsigned int g_done_main;
__device__ unsigned int g_done_final;
__device__ double g_sum;
__device__ unsigned int g_cnt;
__device__ unsigned int g_bar_count;
__device__ volatile unsigned int g_bar_phase;

// ---------------------------------------------------------------------------
__device__ __forceinline__ void gsync() {   // RF_BLOCKS co-resident blocks only
    __syncthreads();
    if (threadIdx.x == 0) {
        unsigned int ph = g_bar_phase;
        __threadfence();
        if (atomicAdd(&g_bar_count, 1u) == RF_BLOCKS - 1u) {
            g_bar_count = 0u;
            __threadfence();
            g_bar_phase = ph + 1u;
        } else {
            while (g_bar_phase == ph) { }
            __threadfence();
        }
    }
    __syncthreads();
}

__device__ __forceinline__ float encode_prob(float logp, bool valid) {
    if (!valid) return 1.0f;
    float pr = __expf(logp);
    unsigned int bb = __float_as_uint(pr);
    if (bb >= ONE_BITS) bb = ALMOST_ONE_BITS;   // 1.0f bits reserved for invalid
    return __uint_as_float(bb);
}

// ---------------------------------------------------------------------------
// Main pass: float2 log-softmax (2 pixels/thread, exactly 8 iterations with
// b = 0..7, hw fixed) + common-path reductions only. Last block decides the
// case and writes the scalar in the common case.
__global__ void __launch_bounds__(256) main_pass(const float* __restrict__ pred,
                                                 const int* __restrict__ target,
                                                 float* __restrict__ out) {
    const int hw2 = blockIdx.x * blockDim.x + threadIdx.x;   // < HWP2 by grid sizing

    unsigned int vcnt = 0, c07 = 0;
    float lsum07 = 0.0f, lsumall = 0.0f;

#pragma unroll
    for (int b = 0; b < BATCH; b++) {
        int i2 = b * HWP2 + hw2;
        int2 tt = __ldcs(reinterpret_cast<const int2*>(target) + i2);
        bool v0 = (tt.x != IGNORE_LBL);
        bool v1 = (tt.y != IGNORE_LBL);
        int tc0 = v0 ? tt.x : 0;
        int tc1 = v1 ? tt.y : 0;

        const float2* p = reinterpret_cast<const float2*>(pred)
                          + (size_t)b * NCLS * HWP2 + hw2;
        float s00 = 0.0f, s01 = 0.0f, s10 = 0.0f, s11 = 0.0f;
        float vt0 = 0.0f, vt1 = 0.0f;
#pragma unroll
        for (int c = 0; c < NCLS; c++) {
            float2 x = __ldcs(p + c * HWP2);
            if (c == tc0) vt0 = x.x;      // predicated selects
            if (c == tc1) vt1 = x.y;
            if (c & 1) { s01 += __expf(x.x); s11 += __expf(x.y); }
            else       { s00 += __expf(x.x); s10 += __expf(x.y); }
        }
        float l0 = vt0 - __logf(s00 + s01);   // logits bounded: no max-subtract
        float l1 = vt1 - __logf(s10 + s11);
        float pr0 = encode_prob(l0, v0);
        float pr1 = encode_prob(l1, v1);

        bool k0 = v0 && (pr0 <= THRESH_F);
        bool k1 = v1 && (pr1 <= THRESH_F);
        vcnt += (v0 ? 1u : 0u) + (v1 ? 1u : 0u);
        c07  += (k0 ? 1u : 0u) + (k1 ? 1u : 0u);
        lsumall += (v0 ? -l0 : 0.0f) + (v1 ? -l1 : 0.0f);
        lsum07  += (k0 ? -l0 : 0.0f) + (k1 ? -l1 : 0.0f);
    }

    // block-reduce 2 uints + 2 floats
    __shared__ unsigned int sh[32], sh2[32];
    __shared__ float sf[32], sf2[32];
    int lane = threadIdx.x & 31, wid = threadIdx.x >> 5;
#pragma unroll
    for (int o = 16; o; o >>= 1) {
        vcnt += __shfl_down_sync(0xffffffffu, vcnt, o);
        c07  += __shfl_down_sync(0xffffffffu, c07, o);
        lsum07 += __shfl_down_sync(0xffffffffu, lsum07, o);
        lsumall += __shfl_down_sync(0xffffffffu, lsumall, o);
    }
    if (lane == 0) { sh[wid] = vcnt; sh2[wid] = c07; sf[wid] = lsum07; sf2[wid] = lsumall; }
    __syncthreads();
    if (wid == 0) {
        unsigned int v = (lane < 8) ? sh[lane] : 0u;
        unsigned int w = (lane < 8) ? sh2[lane] : 0u;
        float f1 = (lane < 8) ? sf[lane] : 0.0f;
        float f2 = (lane < 8) ? sf2[lane] : 0.0f;
#pragma unroll
        for (int o = 16; o; o >>= 1) {
            v += __shfl_down_sync(0xffffffffu, v, o);
            w += __shfl_down_sync(0xffffffffu, w, o);
            f1 += __shfl_down_sync(0xffffffffu, f1, o);
            f2 += __shfl_down_sync(0xffffffffu, f2, o);
        }
        if (lane == 0) {
            atomicAdd(&g_num_valid, v);
            atomicAdd(&g_c07, w);
            atomicAdd(&g_sum07, (double)f1);
            atomicAdd(&g_sumall, (double)f2);
        }
    }

#if defined(CUDA_PROGRAMMATIC_LAUNCH) || (__CUDA_ARCH__ >= 900)
    cudaTriggerProgrammaticLaunchCompletion();   // let refine_final start launching
#endif

    // last block: decide case, emit output (common) or flag the rare path.
    __shared__ bool is_last;
    if (threadIdx.x == 0) {
        __threadfence();
        is_last = (atomicAdd(&g_done_main, 1u) == gridDim.x - 1);
    }
    __syncthreads();
    if (is_last && threadIdx.x == 0) {
        unsigned int nv = g_num_valid;
        unsigned int c07v = g_c07;
        bool do_ohem = (nv >= MIN_KEPT_K);
        if (!do_ohem) {
            unsigned int d = nv < 1u ? 1u : nv;
            out[0] = (float)(g_sumall / (double)d);
            g_skip = 1u;
        } else if (c07v >= MIN_KEPT_K) {    // kth <= 0.7 => threshold == 0.7
            unsigned int d = c07v < 1u ? 1u : c07v;
            out[0] = (float)(g_sum07 / (double)d);
            g_skip = 1u;
        } else {
            g_skip = 2u;
        }
        g_num_valid = 0u; g_c07 = 0u;
        g_sum07 = 0.0; g_sumall = 0.0;
        g_done_main = 0u;
    }
}

// ---------------------------------------------------------------------------
// Rare path only. Pass A recomputes prob + round-1 hist; then scans + rounds
// 2/3 + final reduce. grid == RF_BLOCKS.
__global__ void __launch_bounds__(256) refine_final(const float* __restrict__ pred,
                                                    const int* __restrict__ target,
                                                    float* __restrict__ out) {
#if defined(CUDA_PROGRAMMATIC_LAUNCH) || (__CUDA_ARCH__ >= 900)
    cudaGridDependencySynchronize();   // main_pass writes fully visible
#endif
    if (g_skip == 1u) return;          // common case: out already written

    const int tid = blockIdx.x * blockDim.x + threadIdx.x;
    const int T = RF_BLOCKS * 256;
    __shared__ unsigned int shh[256];

    // zero round-2 bins while pass A hasn't started heavy work
    for (int i = tid; i < 65536; i += T) g_h16[i] = 0u;

    // ---- pass A: recompute prob (scalar), store, round-1 exponent hist ----
    shh[threadIdx.x] = 0u;
    __syncthreads();
    {
        int b = tid / HWP;
        int hw = tid - b * HWP;
        for (int i = tid; i < N_PIX; i += T) {
            int t = target[i];
            bool valid = (t != IGNORE_LBL);
            int tc = valid ? t : 0;
            const float* p = pred + (size_t)b * (NCLS * HWP) + hw;
            float s0 = 0.0f, s1 = 0.0f;
            float vt = 0.0f;
#pragma unroll
            for (int c = 0; c < NCLS; c++) {
                float x = p[c * HWP];
                if (c == tc) vt = x;
                if (c & 1) s1 += __expf(x); else s0 += __expf(x);
            }
            float logp = vt - __logf(s0 + s1);
            float pr = encode_prob(logp, valid);
            g_prob[i] = pr;

            unsigned int bin = __float_as_uint(pr) >> 24;
            unsigned int am = __activemask();
            unsigned int mmask = __match_any_sync(am, bin);
            if ((int)(threadIdx.x & 31) == __ffs(mmask) - 1)
                atomicAdd(&shh[bin], (unsigned int)__popc(mmask));

            hw += T;
            while (hw >= HWP) { hw -= HWP; b++; }
        }
    }
    __syncthreads();
    {
        unsigned int c = shh[threadIdx.x];
        if (c) atomicAdd(&g_h256[threadIdx.x], c);
    }
    gsync();

    // ---- scan round 1 (block 0), zero h256 for round 3 ----
    if (blockIdx.x == 0) {
        int t = threadIdx.x;
        unsigned int cc = g_h256[t];
        shh[t] = cc;
        __syncthreads();
#pragma unroll
        for (int o = 1; o < 256; o <<= 1) {
            unsigned int v = (t >= o) ? shh[t - o] : 0u;
            __syncthreads();
            shh[t] += v;
            __syncthreads();
        }
        unsigned int incl = shh[t];
        unsigned int excl = incl - cc;
        if (excl < MIN_KEPT_K && MIN_KEPT_K <= incl) {
            g_prefix = ((unsigned int)t) << 24;
            g_k = MIN_KEPT_K - excl;
        }
        g_h256[t] = 0u;
        __threadfence();
    }
    gsync();

    // ---- round 2: bits 23..8, filtered on hi-8 prefix, from g_prob ----
    unsigned int prefix = g_prefix;
    unsigned int kk = g_k;
    const uint4* p4u = reinterpret_cast<const uint4*>(g_prob);
    for (int i = tid; i < N4; i += T) {
        uint4 v = p4u[i];
        if ((v.x & 0xFF000000u) == prefix) atomicAdd(&g_h16[(v.x >> 8) & 0xFFFFu], 1u);
        if ((v.y & 0xFF000000u) == prefix) atomicAdd(&g_h16[(v.y >> 8) & 0xFFFFu], 1u);
        if ((v.z & 0xFF000000u) == prefix) atomicAdd(&g_h16[(v.z >> 8) & 0xFFFFu], 1u);
        if ((v.w & 0xFF000000u) == prefix) atomicAdd(&g_h16[(v.w >> 8) & 0xFFFFu], 1u);
    }
    gsync();
    if (blockIdx.x == 0) {
        int t = threadIdx.x;
        int base = t * 256;
        unsigned int lsum = 0;
        const uint4* h4 = reinterpret_cast<const uint4*>(g_h16);
        for (int j = 0; j < 64; j++) {
            uint4 u = h4[(base >> 2) + j];
            lsum += u.x + u.y + u.z + u.w;
        }
        shh[t] = lsum;
        __syncthreads();
#pragma unroll
        for (int o = 1; o < 256; o <<= 1) {
            unsigned int v = (t >= o) ? shh[t - o] : 0u;
            __syncthreads();
            shh[t] += v;
            __syncthreads();
        }
        unsigned int incl = shh[t];
        unsigned int excl = incl - lsum;
        if (excl < kk && kk <= incl && lsum > 0) {
            unsigned int cum = excl;
            for (int b2 = 0; b2 < 256; b2++) {
                unsigned int c = g_h16[base + b2];
                cum += c;
                if (cum >= kk) {
                    g_prefix = prefix | (((unsigned int)(base + b2)) << 8);
                    g_k = kk - (cum - c);
                    break;
                }
            }
        }
        __threadfence();
    }
    gsync();

    // ---- round 3: bits 7..0, filtered on hi-24 prefix ----
    prefix = g_prefix;
    kk = g_k;
    shh[threadIdx.x] = 0u;
    __syncthreads();
    for (int i = tid; i < N4; i += T) {
        uint4 v = p4u[i];
        if ((v.x & 0xFFFFFF00u) == prefix) atomicAdd(&shh[v.x & 255u], 1u);
        if ((v.y & 0xFFFFFF00u) == prefix) atomicAdd(&shh[v.y & 255u], 1u);
        if ((v.z & 0xFFFFFF00u) == prefix) atomicAdd(&shh[v.z & 255u], 1u);
        if ((v.w & 0xFFFFFF00u) == prefix) atomicAdd(&shh[v.w & 255u], 1u);
    }
    __syncthreads();
    {
        unsigned int c = shh[threadIdx.x];
        if (c) atomicAdd(&g_h256[threadIdx.x], c);
    }
    gsync();
    if (blockIdx.x == 0) {
        int t = threadIdx.x;
        unsigned int cc = g_h256[t];
        shh[t] = cc;
        __syncthreads();
#pragma unroll
        for (int o = 1; o < 256; o <<= 1) {
            unsigned int v = (t >= o) ? shh[t - o] : 0u;
            __syncthreads();
            shh[t] += v;
            __syncthreads();
        }
        unsigned int incl = shh[t];
        unsigned int excl = incl - cc;
        if (excl < kk && kk <= incl) {
            g_kth_bits = prefix | (unsigned int)t;
        }
        g_h256[t] = 0u;
        __threadfence();
    }
    gsync();

    // ---- final reduce over g_prob (do_ohem true on this path) ----
    float thr = fmaxf(__uint_as_float(g_kth_bits), THRESH_F);
    float lsum = 0.0f;
    unsigned int cnt = 0;
    const float4* p4 = reinterpret_cast<const float4*>(g_prob);
    for (int i = tid; i < N4; i += T) {
        float4 v = p4[i];
        float pr[4] = {v.x, v.y, v.z, v.w};
#pragma unroll
        for (int e = 0; e < 4; e++) {
            bool valid = (__float_as_uint(pr[e]) != ONE_BITS);
            if (valid && pr[e] <= thr) {
                lsum += -__logf(pr[e]);
                cnt++;
            }
        }
    }
    __shared__ float shf[32];
    __shared__ unsigned int shu[32];
    int lane = threadIdx.x & 31, wid = threadIdx.x >> 5;
#pragma unroll
    for (int o = 16; o; o >>= 1) {
        lsum += __shfl_down_sync(0xffffffffu, lsum, o);
        cnt += __shfl_down_sync(0xffffffffu, cnt, o);
    }
    if (lane == 0) { shf[wid] = lsum; shu[wid] = cnt; }
    __syncthreads();

    __shared__ bool is_last;
    if (threadIdx.x == 0) is_last = false;
    __syncthreads();
    if (wid == 0) {
        float vv = (lane < 8) ? shf[lane] : 0.0f;
        unsigned int u = (lane < 8) ? shu[lane] : 0u;
#pragma unroll
        for (int o = 16; o; o >>= 1) {
            vv += __shfl_down_sync(0xffffffffu, vv, o);
            u += __shfl_down_sync(0xffffffffu, u, o);
        }
        if (lane == 0) {
            atomicAdd(&g_sum, (double)vv);
            atomicAdd(&g_cnt, u);
            __threadfence();
            if (atomicAdd(&g_done_final, 1u) == gridDim.x - 1) is_last = true;
        }
    }
    __syncthreads();
    if (is_last && threadIdx.x == 0) {
        unsigned int c = g_cnt;
        if (c < 1u) c = 1u;
        out[0] = (float)(g_sum / (double)c);
        g_sum = 0.0; g_cnt = 0u; g_done_final = 0u;
    }
}

// ---------------------------------------------------------------------------
extern "C" void kernel_launch(void* const* d_in, const int* in_sizes, int n_in,
                              void* d_out, int out_size) {
    const float* pred = (const float*)d_in[0];
    const int* target = (const int*)d_in[1];
    float* out = (float*)d_out;

    main_pass<<<MAIN_BLOCKS, 256>>>(pred, target, out);

    // PDL launch: refine_final's launch latency overlaps main_pass's tail.
    cudaLaunchConfig_t cfg = {};
    cfg.gridDim = dim3(RF_BLOCKS, 1, 1);
    cfg.blockDim = dim3(256, 1, 1);
    cfg.dynamicSmemBytes = 0;
    cfg.stream = 0;
    cudaLaunchAttribute attrs[1];
    attrs[0].id = cudaLaunchAttributeProgrammaticStreamSerialization;
    attrs[0].val.programmaticStreamSerializationAllowed = 1;
    cfg.attrs = attrs;
    cfg.numAttrs = 1;
    cudaLaunchKernelEx(&cfg, refine_final, pred, target, out);
}

// round 9
// speedup vs baseline: 1.6640x; 1.6640x over previous
#include <cuda_runtime.h>

// Problem constants
#define BATCH 8
#define NCLS 19
#define HH 768
#define WW 768
#define HWP (HH * WW)                 // 589824
#define N_PIX (BATCH * HWP)           // 4718592
#define N4 (N_PIX / 4)                // 1179648
#define IGNORE_LBL 255
#define MIN_KEPT_K 262144u
#define THRESH_F 0.7f
#define ONE_BITS 0x3F800000u
#define ALMOST_ONE_BITS 0x3F7FFFFFu
#define MAIN_BLOCKS 1184
#define MAIN_STRIDE (MAIN_BLOCKS * 256)   // 303104 < HWP
#define RF_BLOCKS 148                 // one block per SM: co-residency guaranteed

// Scratch (no cudaMalloc allowed). Globals are zero at module load; every
// launch self-restores the state it consumes.
__device__ float g_prob[N_PIX];                // rare path only
__device__ unsigned int g_h256[256];           // rare path: rounds 1 & 3
__device__ unsigned int g_h16[65536];          // rare path: round 2
__device__ unsigned int g_prefix;
__device__ unsigned int g_kth_bits;
__device__ unsigned int g_k;
__device__ unsigned int g_skip;                // 1 => out written by main; 2 => refine
__device__ unsigned int g_num_valid;
__device__ unsigned int g_c07;
__device__ double g_sum07;
__device__ double g_sumall;
__device__ unsigned int g_done_main;
__device__ unsigned int g_done_final;
__device__ double g_sum;
__device__ unsigned int g_cnt;
__device__ unsigned int g_bar_count;
__device__ volatile unsigned int g_bar_phase;

// ---------------------------------------------------------------------------
__device__ __forceinline__ void gsync() {   // RF_BLOCKS co-resident blocks only
    __syncthreads();
    if (threadIdx.x == 0) {
        unsigned int ph = g_bar_phase;
        __threadfence();
        if (atomicAdd(&g_bar_count, 1u) == RF_BLOCKS - 1u) {
            g_bar_count = 0u;
            __threadfence();
            g_bar_phase = ph + 1u;
        } else {
            while (g_bar_phase == ph) { }
            __threadfence();
        }
    }
    __syncthreads();
}

__device__ __forceinline__ float encode_prob(float logp, bool valid) {
    if (!valid) return 1.0f;
    float pr = __expf(logp);
    unsigned int bb = __float_as_uint(pr);
    if (bb >= ONE_BITS) bb = ALMOST_ONE_BITS;   // 1.0f bits reserved for invalid
    return __uint_as_float(bb);
}

// ---------------------------------------------------------------------------
// Main pass (R7-proven scalar form): fused log-softmax + common-path
// reductions only. No prob store, no histogram. Last block decides the case
// and writes the scalar in the common case.
__global__ void __launch_bounds__(256) main_pass(const float* __restrict__ pred,
                                                 const int* __restrict__ target,
                                                 float* __restrict__ out) {
    unsigned int vcnt = 0, c07 = 0;
    float lsum07 = 0.0f, lsumall = 0.0f;

    int i0 = blockIdx.x * blockDim.x + threadIdx.x;
    int b = i0 / HWP;                  // single divide; then incremental carry
    int hw = i0 - b * HWP;

    for (int i = i0; i < N_PIX; i += MAIN_STRIDE) {
        int t = __ldcs(target + i);
        bool valid = (t != IGNORE_LBL);
        int tc = valid ? t : 0;

        const float* p = pred + (size_t)b * (NCLS * HWP) + hw;
        float s0 = 0.0f, s1 = 0.0f, s2 = 0.0f, s3 = 0.0f;
        float vt = 0.0f;
#pragma unroll
        for (int c = 0; c < NCLS; c++) {
            float x = __ldcs(p + c * HWP);
            if (c == tc) vt = x;          // predicated select, no dynamic indexing
            if ((c & 3) == 0) s0 += __expf(x);
            else if ((c & 3) == 1) s1 += __expf(x);
            else if ((c & 3) == 2) s2 += __expf(x);
            else s3 += __expf(x);
        }
        float logp = vt - __logf((s0 + s1) + (s2 + s3));   // logits bounded
        float pr = encode_prob(logp, valid);

        bool kept07 = valid && (pr <= THRESH_F);
        vcnt += valid ? 1u : 0u;
        c07  += kept07 ? 1u : 0u;
        lsumall += valid ? -logp : 0.0f;
        lsum07  += kept07 ? -logp : 0.0f;

        hw += MAIN_STRIDE;
        if (hw >= HWP) { hw -= HWP; b++; }
    }

    // block-reduce 2 uints + 2 floats
    __shared__ unsigned int sh[32], sh2[32];
    __shared__ float sf[32], sf2[32];
    int lane = threadIdx.x & 31, wid = threadIdx.x >> 5;
#pragma unroll
    for (int o = 16; o; o >>= 1) {
        vcnt += __shfl_down_sync(0xffffffffu, vcnt, o);
        c07  += __shfl_down_sync(0xffffffffu, c07, o);
        lsum07 += __shfl_down_sync(0xffffffffu, lsum07, o);
        lsumall += __shfl_down_sync(0xffffffffu, lsumall, o);
    }
    if (lane == 0) { sh[wid] = vcnt; sh2[wid] = c07; sf[wid] = lsum07; sf2[wid] = lsumall; }
    __syncthreads();
    if (wid == 0) {
        unsigned int v = (lane < 8) ? sh[lane] : 0u;
        unsigned int w = (lane < 8) ? sh2[lane] : 0u;
        float f1 = (lane < 8) ? sf[lane] : 0.0f;
        float f2 = (lane < 8) ? sf2[lane] : 0.0f;
#pragma unroll
        for (int o = 16; o; o >>= 1) {
            v += __shfl_down_sync(0xffffffffu, v, o);
            w += __shfl_down_sync(0xffffffffu, w, o);
            f1 += __shfl_down_sync(0xffffffffu, f1, o);
            f2 += __shfl_down_sync(0xffffffffu, f2, o);
        }
        if (lane == 0) {
            atomicAdd(&g_num_valid, v);
            atomicAdd(&g_c07, w);
            atomicAdd(&g_sum07, (double)f1);
            atomicAdd(&g_sumall, (double)f2);
        }
    }

    // last block: decide case, emit output (common) or flag the rare path.
    __shared__ bool is_last;
    if (threadIdx.x == 0) {
        __threadfence();
        is_last = (atomicAdd(&g_done_main, 1u) == gridDim.x - 1);
    }
    __syncthreads();
    if (is_last && threadIdx.x == 0) {
        unsigned int nv = g_num_valid;
        unsigned int c07v = g_c07;
        bool do_ohem = (nv >= MIN_KEPT_K);
        if (!do_ohem) {
            unsigned int d = nv < 1u ? 1u : nv;
            out[0] = (float)(g_sumall / (double)d);
            g_skip = 1u;
        } else if (c07v >= MIN_KEPT_K) {    // kth <= 0.7 => threshold == 0.7
            unsigned int d = c07v < 1u ? 1u : c07v;
            out[0] = (float)(g_sum07 / (double)d);
            g_skip = 1u;
        } else {
            g_skip = 2u;
        }
        g_num_valid = 0u; g_c07 = 0u;
        g_sum07 = 0.0; g_sumall = 0.0;
        g_done_main = 0u;
    }
}

// ---------------------------------------------------------------------------
// Rare path only. Pass A recomputes prob + round-1 hist; then scans + rounds
// 2/3 + final reduce. grid == RF_BLOCKS.
__global__ void __launch_bounds__(256) refine_final(const float* __restrict__ pred,
                                                    const int* __restrict__ target,
                                                    float* __restrict__ out) {
    if (g_skip == 1u) return;          // common case: out already written

    const int tid = blockIdx.x * blockDim.x + threadIdx.x;
    const int T = RF_BLOCKS * 256;
    __shared__ unsigned int shh[256];

    // zero round-2 bins before heavy work
    for (int i = tid; i < 65536; i += T) g_h16[i] = 0u;

    // ---- pass A: recompute prob (scalar), store, round-1 exponent hist ----
    shh[threadIdx.x] = 0u;
    __syncthreads();
    {
        int b = tid / HWP;
        int hw = tid - b * HWP;
        for (int i = tid; i < N_PIX; i += T) {
            int t = target[i];
            bool valid = (t != IGNORE_LBL);
            int tc = valid ? t : 0;
            const float* p = pred + (size_t)b * (NCLS * HWP) + hw;
            float s0 = 0.0f, s1 = 0.0f;
            float vt = 0.0f;
#pragma unroll
            for (int c = 0; c < NCLS; c++) {
                float x = p[c * HWP];
                if (c == tc) vt = x;
                if (c & 1) s1 += __expf(x); else s0 += __expf(x);
            }
            float logp = vt - __logf(s0 + s1);
            float pr = encode_prob(logp, valid);
            g_prob[i] = pr;

            unsigned int bin = __float_as_uint(pr) >> 24;
            unsigned int am = __activemask();
            unsigned int mmask = __match_any_sync(am, bin);
            if ((int)(threadIdx.x & 31) == __ffs(mmask) - 1)
                atomicAdd(&shh[bin], (unsigned int)__popc(mmask));

            hw += T;
            while (hw >= HWP) { hw -= HWP; b++; }
        }
    }
    __syncthreads();
    {
        unsigned int c = shh[threadIdx.x];
        if (c) atomicAdd(&g_h256[threadIdx.x], c);
    }
    gsync();

    // ---- scan round 1 (block 0), zero h256 for round 3 ----
    if (blockIdx.x == 0) {
        int t = threadIdx.x;
        unsigned int cc = g_h256[t];
        shh[t] = cc;
        __syncthreads();
#pragma unroll
        for (int o = 1; o < 256; o <<= 1) {
            unsigned int v = (t >= o) ? shh[t - o] : 0u;
            __syncthreads();
            shh[t] += v;
            __syncthreads();
        }
        unsigned int incl = shh[t];
        unsigned int excl = incl - cc;
        if (excl < MIN_KEPT_K && MIN_KEPT_K <= incl) {
            g_prefix = ((unsigned int)t) << 24;
            g_k = MIN_KEPT_K - excl;
        }
        g_h256[t] = 0u;
        __threadfence();
    }
    gsync();

    // ---- round 2: bits 23..8, filtered on hi-8 prefix, from g_prob ----
    unsigned int prefix = g_prefix;
    unsigned int kk = g_k;
    const uint4* p4u = reinterpret_cast<const uint4*>(g_prob);
    for (int i = tid; i < N4; i += T) {
        uint4 v = p4u[i];
        if ((v.x & 0xFF000000u) == prefix) atomicAdd(&g_h16[(v.x >> 8) & 0xFFFFu], 1u);
        if ((v.y & 0xFF000000u) == prefix) atomicAdd(&g_h16[(v.y >> 8) & 0xFFFFu], 1u);
        if ((v.z & 0xFF000000u) == prefix) atomicAdd(&g_h16[(v.z >> 8) & 0xFFFFu], 1u);
        if ((v.w & 0xFF000000u) == prefix) atomicAdd(&g_h16[(v.w >> 8) & 0xFFFFu], 1u);
    }
    gsync();
    if (blockIdx.x == 0) {
        int t = threadIdx.x;
        int base = t * 256;
        unsigned int lsum = 0;
        const uint4* h4 = reinterpret_cast<const uint4*>(g_h16);
        for (int j = 0; j < 64; j++) {
            uint4 u = h4[(base >> 2) + j];
            lsum += u.x + u.y + u.z + u.w;
        }
        shh[t] = lsum;
        __syncthreads();
#pragma unroll
        for (int o = 1; o < 256; o <<= 1) {
            unsigned int v = (t >= o) ? shh[t - o] : 0u;
            __syncthreads();
            shh[t] += v;
            __syncthreads();
        }
        unsigned int incl = shh[t];
        unsigned int excl = incl - lsum;
        if (excl < kk && kk <= incl && lsum > 0) {
            unsigned int cum = excl;
            for (int b2 = 0; b2 < 256; b2++) {
                unsigned int c = g_h16[base + b2];
                cum += c;
                if (cum >= kk) {
                    g_prefix = prefix | (((unsigned int)(base + b2)) << 8);
                    g_k = kk - (cum - c);
                    break;
                }
            }
        }
        __threadfence();
    }
    gsync();

    // ---- round 3: bits 7..0, filtered on hi-24 prefix ----
    prefix = g_prefix;
    kk = g_k;
    shh[threadIdx.x] = 0u;
    __syncthreads();
    for (int i = tid; i < N4; i += T) {
        uint4 v = p4u[i];
        if ((v.x & 0xFFFFFF00u) == prefix) atomicAdd(&shh[v.x & 255u], 1u);
        if ((v.y & 0xFFFFFF00u) == prefix) atomicAdd(&shh[v.y & 255u], 1u);
        if ((v.z & 0xFFFFFF00u) == prefix) atomicAdd(&shh[v.z & 255u], 1u);
        if ((v.w & 0xFFFFFF00u) == prefix) atomicAdd(&shh[v.w & 255u], 1u);
    }
    __syncthreads();
    {
        unsigned int c = shh[threadIdx.x];
        if (c) atomicAdd(&g_h256[threadIdx.x], c);
    }
    gsync();
    if (blockIdx.x == 0) {
        int t = threadIdx.x;
        unsigned int cc = g_h256[t];
        shh[t] = cc;
        __syncthreads();
#pragma unroll
        for (int o = 1; o < 256; o <<= 1) {
            unsigned int v = (t >= o) ? shh[t - o] : 0u;
            __syncthreads();
            shh[t] += v;
            __syncthreads();
        }
        unsigned int incl = shh[t];
        unsigned int excl = incl - cc;
        if (excl < kk && kk <= incl) {
            g_kth_bits = prefix | (unsigned int)t;
        }
        g_h256[t] = 0u;
        __threadfence();
    }
    gsync();

    // ---- final reduce over g_prob (do_ohem true on this path) ----
    float thr = fmaxf(__uint_as_float(g_kth_bits), THRESH_F);
    float lsum = 0.0f;
    unsigned int cnt = 0;
    const float4* p4 = reinterpret_cast<const float4*>(g_prob);
    for (int i = tid; i < N4; i += T) {
        float4 v = p4[i];
        float pr[4] = {v.x, v.y, v.z, v.w};
#pragma unroll
        for (int e = 0; e < 4; e++) {
            bool valid = (__float_as_uint(pr[e]) != ONE_BITS);
            if (valid && pr[e] <= thr) {
                lsum += -__logf(pr[e]);
                cnt++;
            }
        }
    }
    __shared__ float shf[32];
    __shared__ unsigned int shu[32];
    int lane = threadIdx.x & 31, wid = threadIdx.x >> 5;
#pragma unroll
    for (int o = 16; o; o >>= 1) {
        lsum += __shfl_down_sync(0xffffffffu, lsum, o);
        cnt += __shfl_down_sync(0xffffffffu, cnt, o);
    }
    if (lane == 0) { shf[wid] = lsum; shu[wid] = cnt; }
    __syncthreads();

    __shared__ bool is_last;
    if (threadIdx.x == 0) is_last = false;
    __syncthreads();
    if (wid == 0) {
        float vv = (lane < 8) ? shf[lane] : 0.0f;
        unsigned int u = (lane < 8) ? shu[lane] : 0u;
#pragma unroll
        for (int o = 16; o; o >>= 1) {
            vv += __shfl_down_sync(0xffffffffu, vv, o);
            u += __shfl_down_sync(0xffffffffu, u, o);
        }
        if (lane == 0) {
            atomicAdd(&g_sum, (double)vv);
            atomicAdd(&g_cnt, u);
            __threadfence();
            if (atomicAdd(&g_done_final, 1u) == gridDim.x - 1) is_last = true;
        }
    }
    __syncthreads();
    if (is_last && threadIdx.x == 0) {
        unsigned int c = g_cnt;
        if (c < 1u) c = 1u;
        out[0] = (float)(g_sum / (double)c);
        g_sum = 0.0; g_cnt = 0u; g_done_final = 0u;
    }
}

// ---------------------------------------------------------------------------
extern "C" void kernel_launch(void* const* d_in, const int* in_sizes, int n_in,
                              void* d_out, int out_size) {
    const float* pred = (const float*)d_in[0];
    const int* target = (const int*)d_in[1];
    float* out = (float*)d_out;

    main_pass<<<MAIN_BLOCKS, 256>>>(pred, target, out);
    refine_final<<<RF_BLOCKS, 256>>>(pred, target, out);
}